// round 13
// baseline (speedup 1.0000x reference)
#include <cuda_runtime.h>
#include <cstdint>

// ---------------------------------------------------------------------------
// DiverseRegDCConv2d: per-sample dynamically-generated 3x3 conv.
//   wgen[b,o,c,kh,kw] = sum_n se[b,n] * weight[(o*C+c)*9+kh*3+kw, n]
//   out[b,o,h,w] = sum_{c,kh,kw} wgen[b,o,c,kh,kw] * x[b,c,h+kh-1,w+kw-1] + bias[o]
// B=32, C=O=256, H=W=28, K=3, NUM=8.
// ---------------------------------------------------------------------------

#define BB   32
#define CIN  256
#define COUT 256
#define HH   28
#define WW   28

typedef unsigned long long ULL;

// Stage-1 output: weights pre-DUPLICATED as (w,w) ULLs, o-major per tap:
//   [b][ob:8][c:256][tap:9][o:32]  ULLs  (151 MB)
__device__ ULL g_w2[(size_t)BB * 8 * 256 * 9 * 32];
// Stage-0 output: input rows in dual alignment, cp16-ready (58.7 MB):
//   [b][c][h][64]: f0..27 = cols 0..27 | f28..31 = 0 | f32 = 0 (col -1) |
//                  f33..60 = cols 0..27 | f61..63 = 0
__device__ float g_xpad[(size_t)BB * CIN * HH * 64];

__device__ __forceinline__ ULL pack2(float lo, float hi) {
    ULL r; asm("mov.b64 %0, {%1, %2};" : "=l"(r) : "f"(lo), "f"(hi)); return r;
}
__device__ __forceinline__ ULL ffma2(ULL a, ULL b, ULL c) {
    ULL d; asm("fma.rn.f32x2 %0, %1, %2, %3;" : "=l"(d) : "l"(a), "l"(b), "l"(c)); return d;
}
__device__ __forceinline__ ULL fadd2(ULL a, ULL b) {
    ULL d; asm("add.rn.f32x2 %0, %1, %2;" : "=l"(d) : "l"(a), "l"(b)); return d;
}
__device__ __forceinline__ float2 unpack2(ULL v) {
    float2 f; asm("mov.b64 {%0, %1}, %2;" : "=f"(f.x), "=f"(f.y) : "l"(v)); return f;
}
__device__ __forceinline__ void cp16(uint32_t dst, const void* src) {
    asm volatile("cp.async.ca.shared.global [%0], [%1], 16;\n"
                 :: "r"(dst), "l"(src) : "memory");
}
#define CP_COMMIT() asm volatile("cp.async.commit_group;\n" ::: "memory")
#define CP_WAIT0()  asm volatile("cp.async.wait_group 0;\n" ::: "memory")

// ---------------------------------------------------------------------------
// Stage 0: build dual-aligned padded input rows (pure-cp16 conv fills).
// ---------------------------------------------------------------------------
__global__ void xpad_kernel(const float* __restrict__ x) {
    int gid = blockIdx.x * 256 + threadIdx.x;     // < 3,670,016
    int row = gid >> 4;                            // (b*256+c)*28+h
    int s   = gid & 15;
    const float* src = x + (size_t)row * WW;
    float4 v;
    if (s < 7) {
        v = *(const float4*)(src + 4 * s);         // cols 4s..4s+3 (aligned)
    } else if (s == 7) {
        v = make_float4(0.f, 0.f, 0.f, 0.f);
    } else {
        float t[4];
        #pragma unroll
        for (int m = 0; m < 4; ++m) {
            int col = 4 * s + m - 33;              // f = 4s+m, col = f-33
            t[m] = ((unsigned)col < (unsigned)WW) ? __ldg(src + col) : 0.f;
        }
        v = make_float4(t[0], t[1], t[2], t[3]);
    }
    *(float4*)(g_xpad + (size_t)row * 64 + 4 * s) = v;
}

// ---------------------------------------------------------------------------
// Stage 1: weight generation, duplicated (w,w) ULLs, o-major per tap.
// Block = one (ob, c): 288 threads = 9 taps x 32 o; thread computes its tap
// once per sample. STG.64 coalesced (warp = 32 consecutive o).
// ---------------------------------------------------------------------------
__global__ void wgen_kernel(const float* __restrict__ wbank,
                            const float* __restrict__ se) {
    __shared__ float s_se[BB * 8];
    int tid = threadIdx.x;                 // 0..287
    if (tid < 256) s_se[tid] = se[tid];
    __syncthreads();

    const int c   = blockIdx.x & 255;
    const int ob  = blockIdx.x >> 8;       // 0..7
    const int t   = tid >> 5;              // tap 0..8
    const int o31 = tid & 31;
    const int o   = ob * 32 + o31;

    const float4* src = (const float4*)wbank + ((size_t)(o * CIN + c) * 9 + t) * 2;
    float4 w0 = src[0];
    float4 w1 = src[1];

    ULL* dst = g_w2 + ((size_t)ob * 256 + c) * 288 + tid;
    const size_t bstr = (size_t)8 * 256 * 288;
    for (int b = 0; b < BB; ++b) {
        const float* s = &s_se[b * 8];
        float v = w0.x * s[0];
        v = fmaf(w0.y, s[1], v);
        v = fmaf(w0.z, s[2], v);
        v = fmaf(w0.w, s[3], v);
        v = fmaf(w1.x, s[4], v);
        v = fmaf(w1.y, s[5], v);
        v = fmaf(w1.z, s[6], v);
        v = fmaf(w1.w, s[7], v);
        dst[(size_t)b * bstr] = pack2(v, v);
    }
}

// ---------------------------------------------------------------------------
// Stage 2: direct conv (R11 shape). Block (16,14)=224 thr: 32 o x 7 rows x 28.
// Thread: 2 o (tx, tx+16) x 1 row (ty>>1) x half-row (ty&1). 4 blocks/SM.
// Input smem rows (XR=72, 72%32=8 -> conflict-free): A at f0..27 (col c @ f c),
// B at f36..67 (col c @ f 37+c; f36 = col -1 = 0).
// Weights in smem as dup'd ULLs [cc][tap:9][o:32]: 1 LDS.64/tap/o, 0 packs.
// ---------------------------------------------------------------------------
#define CCK  4                       // channels per chunk (64 chunks)
#define NRW  9                       // staged rows (7 + 2 halo)
#define XR   72                      // floats per staged input row
#define XCH  (CCK * NRW * XR)        // 2592 floats per input buffer
#define WCHU (CCK * 9 * 32)          // 1152 ULLs per weight buffer
#define SMEM_BYTES (2 * WCHU * 8 + 2 * XCH * 4)   // 18432 + 20736 = 39168 B

__global__ __launch_bounds__(224, 4)
void dconv_kernel(const float* __restrict__ bias,
                  float* __restrict__ out) {
    extern __shared__ ULL smem_u[];
    ULL*   ws = smem_u;                        // [2][WCHU]
    float* xs = (float*)(smem_u + 2 * WCHU);   // [2][XCH]

    const int tx  = threadIdx.x;     // 0..15 : o-lane
    const int ty  = threadIdx.y;     // 0..13
    const int tid = ty * 16 + tx;
    const int row = ty >> 1;         // 0..6
    const int j0  = 7 * (ty & 1);    // col-half base

    const int b       = blockIdx.y;
    const int ob      = blockIdx.x >> 2;   // 0..7
    const int rb      = blockIdx.x & 3;    // 0..3
    const int oBase   = ob * 32;
    const int rowBase = rb * 7;

    const char* wsrc = (const char*)(g_w2 + (((size_t)b * 8 + ob) * 256) * 288);
    const char* xsrc = (const char*)(g_xpad + (size_t)b * CIN * HH * 64);

    const uint32_t ws_u = (uint32_t)__cvta_generic_to_shared(ws);
    const uint32_t xs_u = (uint32_t)__cvta_generic_to_shared(xs);

    // Zero input buffers once (invalid halo rows stay zero forever).
    for (int i = tid; i < (2 * XCH) / 4; i += 224)
        ((float4*)xs)[i] = make_float4(0.f, 0.f, 0.f, 0.f);
    __syncthreads();

    // ---- precompute fill descriptors (reused every chunk) ----
    // input: 540 slots = 4cc x 9 rows x 15 cp16
    uint32_t in_dst[3]; uint32_t in_off[3]; bool in_ok[3];
    #pragma unroll
    for (int m = 0; m < 3; ++m) {
        int idx = tid + 224 * m;
        int cc = idx / 135, rem = idx % 135, rw = rem / 15, s = rem % 15;
        int ih = rowBase - 1 + rw;
        in_ok[m] = (idx < 540) && ((unsigned)ih < (unsigned)HH);
        int dco = (s < 7) ? s * 4 : 36 + (s - 7) * 4;
        int sco = (s < 7) ? s * 4 : 32 + (s - 7) * 4;
        in_dst[m] = (uint32_t)(((cc * NRW + rw) * XR + dco) * 4);
        in_off[m] = (uint32_t)((((cc * HH + (ih < 0 ? 0 : ih)) * 64) + sco) * 4);
    }
    // weights: 576 cp16 slots
    const bool w_ok2 = (tid < 128);

    ULL acc0[7], acc1[7];
    #pragma unroll
    for (int j = 0; j < 7; ++j) { acc0[j] = 0ull; acc1[j] = 0ull; }

    // ---- prologue: fill chunk 0 into buffer 0 (all cp16)
    {
        cp16(ws_u + tid * 16, wsrc + tid * 16);
        cp16(ws_u + (tid + 224) * 16, wsrc + (size_t)(tid + 224) * 16);
        if (w_ok2) cp16(ws_u + (tid + 448) * 16, wsrc + (size_t)(tid + 448) * 16);
        #pragma unroll
        for (int m = 0; m < 3; ++m)
            if (in_ok[m]) cp16(xs_u + in_dst[m], xsrc + in_off[m]);
        CP_COMMIT();
    }

    const uint32_t XSTRIDE = CCK * HH * 64 * 4;   // 28672 B per chunk
    const uint32_t WSTRIDE = WCHU * 8;            // 9216 B per chunk

    for (int k = 0; k < CIN / CCK; ++k) {
        CP_WAIT0();
        __syncthreads();

        if (k < CIN / CCK - 1) {
            const uint32_t wd = ws_u + ((k + 1) & 1) * (WCHU * 8);
            const uint32_t xd = xs_u + ((k + 1) & 1) * (XCH * 4);
            const char* wkb = wsrc + (size_t)(k + 1) * WSTRIDE;
            const char* xkb = xsrc + (size_t)(k + 1) * XSTRIDE;
            cp16(wd + tid * 16, wkb + tid * 16);
            cp16(wd + (tid + 224) * 16, wkb + (size_t)(tid + 224) * 16);
            if (w_ok2) cp16(wd + (tid + 448) * 16, wkb + (size_t)(tid + 448) * 16);
            #pragma unroll
            for (int m = 0; m < 3; ++m)
                if (in_ok[m]) cp16(xd + in_dst[m], xkb + in_off[m]);
            CP_COMMIT();
        }

        const ULL*   wsb = ws + (k & 1) * WCHU;
        const float* xsb = xs + (k & 1) * XCH;

        #pragma unroll
        for (int cc = 0; cc < CCK; ++cc) {
            #pragma unroll
            for (int r = 0; r < 3; ++r) {
                // 6 conflict-free LDS.64, zero packs
                const ULL* wp = wsb + (cc * 9 + r * 3) * 32;
                ULL W00 = wp[tx],      W01 = wp[tx + 16];        // kw=0
                ULL W10 = wp[32 + tx], W11 = wp[32 + tx + 16];   // kw=1
                ULL W20 = wp[64 + tx], W21 = wp[64 + tx + 16];   // kw=2
                const float* xr = xsb + (cc * NRW + row + r) * XR;
                const ULL* Aq = (const ULL*)xr;
                const ULL* Bq = (const ULL*)(xr + 36);
                ULL b0 = Bq[j0];
                #pragma unroll
                for (int jj = 0; jj < 7; ++jj) {
                    ULL a  = Aq[j0 + jj];
                    ULL b1 = Bq[j0 + jj + 1];
                    acc0[jj] = ffma2(W20, b1,
                               ffma2(W10, a,
                               ffma2(W00, b0, acc0[jj])));
                    acc1[jj] = ffma2(W21, b1,
                               ffma2(W11, a,
                               ffma2(W01, b0, acc1[jj])));
                    b0 = b1;
                }
            }
        }
    }

    // ---- epilogue: bias + store (2 o x 7 float2 each)
    const int o0 = oBase + tx, o1 = o0 + 16;
    const int h  = rowBase + row;
    float bv0 = bias[o0], bv1 = bias[o1];
    ULL bb0 = pack2(bv0, bv0), bb1 = pack2(bv1, bv1);
    float2* p0 = (float2*)(out + (((size_t)b * COUT + o0) * HH + h) * WW + 2 * j0);
    float2* p1 = (float2*)(out + (((size_t)b * COUT + o1) * HH + h) * WW + 2 * j0);
    #pragma unroll
    for (int jj = 0; jj < 7; ++jj) {
        p0[jj] = unpack2(fadd2(acc0[jj], bb0));
        p1[jj] = unpack2(fadd2(acc1[jj], bb1));
    }
}

// ---------------------------------------------------------------------------
// Harness entry. Inputs (metadata order): inputs, inputs_se, weight, bias.
// ---------------------------------------------------------------------------
extern "C" void kernel_launch(void* const* d_in, const int* in_sizes, int n_in,
                              void* d_out, int out_size) {
    const float* x    = (const float*)d_in[0];   // [32,256,28,28]
    const float* se   = (const float*)d_in[1];   // [32,8]
    const float* wbk  = (const float*)d_in[2];   // [589824,8]
    const float* bias = (const float*)d_in[3];   // [256]
    float* out = (float*)d_out;                  // [32,256,28,28]

    cudaFuncSetAttribute(dconv_kernel,
                         cudaFuncAttributePreferredSharedMemoryCarveout, 100);

    xpad_kernel<<<(BB * CIN * HH * 16) / 256, 256>>>(x);   // 14336 blocks
    wgen_kernel<<<8 * 256, 288>>>(wbk, se);                // 2048 blocks

    dim3 grid(32, BB);          // x: 8 o-blocks * 4 row-blocks, y: batch
    dim3 block(16, 14);         // 224 threads
    dconv_kernel<<<grid, block, SMEM_BYTES>>>(bias, out);
}

// round 15
// speedup vs baseline: 2.3402x; 2.3402x over previous
#include <cuda_runtime.h>
#include <cuda_bf16.h>
#include <cstdint>

// ---------------------------------------------------------------------------
// DiverseRegDCConv2d via warp-level HMMA (mma.sync m16n8k16 bf16) implicit GEMM.
//   Per sample b:  D[o, n] = sum_{tap,c} W[o,c,tap] * T[n + tapoff(tap), c]
// n indexes the zero-padded 30x30 pixel space (n = oh*30 + ow'), so each tap
// is a row offset (30*kh + kw) into one shared T slab.
// Precision: bf16 hi/lo split, 3 accumulating passes (hh, hl, lh).
// B=32, C=O=256, H=W=28, K=3, NUM=8.
// ---------------------------------------------------------------------------

#define BB   32
#define CIN  256
#define COUT 256
#define HH   28
#define WW   28

typedef unsigned long long ULL;

// intermediate generated weights fp32: [b][o:256][tap:9][c:256]  (75.5 MB)
__device__ float g_wgen[(size_t)BB * 256 * 9 * 256];

// A fragments, mma-ready: [b][mt:2][stage:36(=cblk*9+tap)][split:2][frag:8][ku:4][lane:32] uint4
__device__ uint4 g_A[(size_t)BB * 2 * 36 * 2 * 1024];          // 75.5 MB

// T slabs: [split:2][b][cblk:4][p:912][c:64] bf16, 128B rows, granule ^ (p&7).
// p = i*30 + j over the padded 30x30 image; rows 900..911 zero guards. 29.9 MB
#define T_ROWS 912
#define T_SPLIT_EL ((size_t)BB * 4 * T_ROWS * 64)
__device__ __nv_bfloat16 g_T[2 * T_SPLIT_EL];

// ---------------- helpers ----------------------------------------------------
__device__ __forceinline__ void cp16(uint32_t dst, const void* src) {
    asm volatile("cp.async.ca.shared.global [%0], [%1], 16;\n"
                 :: "r"(dst), "l"(src) : "memory");
}
#define CP_COMMIT() asm volatile("cp.async.commit_group;\n" ::: "memory")

__device__ __forceinline__ void lds128(uint32_t* q, uint32_t a) {
    asm volatile("ld.shared.v4.b32 {%0,%1,%2,%3}, [%4];"
                 : "=r"(q[0]), "=r"(q[1]), "=r"(q[2]), "=r"(q[3]) : "r"(a));
}
__device__ __forceinline__ uint32_t lds32(uint32_t a) {
    uint32_t v; asm volatile("ld.shared.b32 %0, [%1];" : "=r"(v) : "r"(a));
    return v;
}
__device__ __forceinline__ void mma_bf16(float* d, const uint32_t* a,
                                         const uint32_t* bfr) {
    asm volatile(
        "mma.sync.aligned.m16n8k16.row.col.f32.bf16.bf16.f32 "
        "{%0,%1,%2,%3}, {%4,%5,%6,%7}, {%8,%9}, {%0,%1,%2,%3};"
        : "+f"(d[0]), "+f"(d[1]), "+f"(d[2]), "+f"(d[3])
        : "r"(a[0]), "r"(a[1]), "r"(a[2]), "r"(a[3]),
          "r"(bfr[0]), "r"(bfr[1]));
}
__device__ __forceinline__ void split2(float x, float y, uint32_t& hi, uint32_t& lo) {
    __nv_bfloat16 h0 = __float2bfloat16(x);
    __nv_bfloat16 h1 = __float2bfloat16(y);
    __nv_bfloat16 l0 = __float2bfloat16(x - __bfloat162float(h0));
    __nv_bfloat16 l1 = __float2bfloat16(y - __bfloat162float(h1));
    hi = ((uint32_t)__bfloat16_as_ushort(h1) << 16) | __bfloat16_as_ushort(h0);
    lo = ((uint32_t)__bfloat16_as_ushort(l1) << 16) | __bfloat16_as_ushort(l0);
}

// ---------------------------------------------------------------------------
// Stage 0: T slabs. Block = (i 0..30, cblk, b); i==30 zeroes guard rows.
// ---------------------------------------------------------------------------
__global__ void xprep_kernel(const float* __restrict__ x) {
    __shared__ float sm[64 * 28];
    const int i = blockIdx.x, cblk = blockIdx.y, b = blockIdx.z;
    const int tid = threadIdx.x;

    if (i == 30) {
        for (int idx = tid; idx < 12 * 64; idx += 256) {
            int rr = idx / 64, slot = idx % 64;
            size_t base = (((size_t)b * 4 + cblk) * T_ROWS + 900 + rr) * 64 + slot;
            g_T[base] = __float2bfloat16(0.f);
            g_T[T_SPLIT_EL + base] = __float2bfloat16(0.f);
        }
        return;
    }
    const bool iv = (i >= 1 && i <= 28);
    if (iv) {
        for (int idx = tid; idx < 64 * 28; idx += 256) {
            int c_l = idx / 28, j1 = idx % 28;
            sm[idx] = x[(((size_t)b * 256 + cblk * 64 + c_l) * HH + (i - 1)) * WW + j1];
        }
    }
    __syncthreads();
    for (int idx = tid; idx < 30 * 64; idx += 256) {
        int j = idx / 64, c_l = idx % 64;
        float v = 0.f;
        if (iv && j >= 1 && j <= 28) v = sm[c_l * 28 + (j - 1)];
        int p = i * 30 + j;
        int slot = (((c_l >> 3) ^ (p & 7)) << 3) | (c_l & 7);
        __nv_bfloat16 hi = __float2bfloat16(v);
        __nv_bfloat16 lo = __float2bfloat16(v - __bfloat162float(hi));
        size_t base = (((size_t)b * 4 + cblk) * T_ROWS + p) * 64 + slot;
        g_T[base] = hi;
        g_T[T_SPLIT_EL + base] = lo;
    }
}

// ---------------------------------------------------------------------------
// Stage 1: weight generation. Thread = (o, c), bank row in regs, loops b.
// Writes [b][o][tap][c] fp32 (warp = 32 consecutive c -> coalesced).
// ---------------------------------------------------------------------------
__global__ void wgen_kernel(const float* __restrict__ wbank,
                            const float* __restrict__ se) {
    __shared__ float s_se[256];
    const int tid = threadIdx.x;
    s_se[tid] = se[tid];
    __syncthreads();

    const int o = (blockIdx.x >> 3) * 8 + (tid >> 5);
    const int c = (blockIdx.x & 7) * 32 + (tid & 31);

    const float4* src = (const float4*)wbank + (size_t)(o * 256 + c) * 18;
    float4 w4[18];
    #pragma unroll
    for (int i = 0; i < 18; ++i) w4[i] = src[i];
    const float* w = (const float*)w4;

    for (int b = 0; b < BB; ++b) {
        const float* s = &s_se[b * 8];
        #pragma unroll
        for (int t = 0; t < 9; ++t) {
            float v = w[t * 8 + 0] * s[0];
            v = fmaf(w[t * 8 + 1], s[1], v);
            v = fmaf(w[t * 8 + 2], s[2], v);
            v = fmaf(w[t * 8 + 3], s[3], v);
            v = fmaf(w[t * 8 + 4], s[4], v);
            v = fmaf(w[t * 8 + 5], s[5], v);
            v = fmaf(w[t * 8 + 6], s[6], v);
            v = fmaf(w[t * 8 + 7], s[7], v);
            g_wgen[(((size_t)b * 256 + o) * 9 + t) * 256 + c] = v;
        }
    }
}

// ---------------------------------------------------------------------------
// Stage 2: pack wgen into mma A-fragment order (hi & lo splits).
// m16n8k16 A frag (row-major): lane L (r=L>>2, t=L&3):
//   reg0 = A[r][2t,2t+1]; reg1 = A[r+8][2t,2t+1]; reg2 = A[r][2t+8,+9]; reg3 = A[r+8][2t+8,+9]
// ---------------------------------------------------------------------------
__global__ void pack_kernel() {
    int idx = blockIdx.x * 256 + threadIdx.x;     // < 2,359,296
    int lane = idx & 31;  int x1 = idx >> 5;
    int ku   = x1 & 3;    int x2 = x1 >> 2;
    int frag = x2 & 7;    int x3 = x2 >> 3;
    int tap  = x3 % 9;    int x4 = x3 / 9;
    int cblk = x4 & 3;    int x5 = x4 >> 2;
    int mt   = x5 & 1;    int b  = x5 >> 1;

    int r = lane >> 2, t = lane & 3;
    int o0 = mt * 128 + frag * 16 + r;
    int c0 = cblk * 64 + ku * 16 + 2 * t;
    size_t row0 = (((size_t)b * 256 + o0) * 9 + tap) * 256;
    size_t row8 = row0 + (size_t)8 * 9 * 256;
    float2 v0 = *(const float2*)&g_wgen[row0 + c0];
    float2 v1 = *(const float2*)&g_wgen[row8 + c0];
    float2 v2 = *(const float2*)&g_wgen[row0 + c0 + 8];
    float2 v3 = *(const float2*)&g_wgen[row8 + c0 + 8];

    uint4 hi, lo;
    split2(v0.x, v0.y, hi.x, lo.x);
    split2(v1.x, v1.y, hi.y, lo.y);
    split2(v2.x, v2.y, hi.z, lo.z);
    split2(v3.x, v3.y, hi.w, lo.w);

    size_t sb = (((size_t)(b * 2 + mt) * 36 + (cblk * 9 + tap)) * 2) * 1024
                + (frag * 4 + ku) * 32 + lane;
    g_A[sb] = hi;
    g_A[sb + 1024] = lo;
}

// ---------------------------------------------------------------------------
// Stage 3: HMMA GEMM. Grid (ht:7, mt:2, b:32), 192 thr = 6 warps (2M x 3N).
// Warp tile m64 x n40 (4 m16 x 5 n8 units). 36 k-stages (cblk*9+tap), k=64.
// A double-buffered cp.async; B slab (182 rows x 128B x 2 splits) per cblk,
// single-buffered. 3 passes: (Ah,Bh), (Ah,Bl), (Al,Bh).
// ---------------------------------------------------------------------------
#define A_SPLIT_B 16384
#define A_STAGE_B 32768
#define B_SPLIT_B 23296                    // 182 * 128
#define DYN_BYTES (1024 + 2 * A_STAGE_B + 2 * B_SPLIT_B)   // 113152

__global__ __launch_bounds__(192, 2)
void conv_mma_kernel(const float* __restrict__ bias,
                     float* __restrict__ out) {
    extern __shared__ char dyn[];
    const int tid = threadIdx.x;
    const int L = tid & 31, wid = tid >> 5;
    const int wm = wid & 1, wn = wid >> 1;    // wn 0..2
    const int r = L >> 2, t = L & 3;
    const int ht = blockIdx.x, mt = blockIdx.y, b = blockIdx.z;

    const uint32_t dynu = (uint32_t)__cvta_generic_to_shared(dyn);
    const uint32_t al = (dynu + 1023) & ~1023u;
    const uint32_t aBufs = al;
    const uint32_t bBufs = al + 2 * A_STAGE_B;

    const uint4* srcA = g_A + ((size_t)(b * 2 + mt) * 36) * 2048;
    const int p0 = ht * 120;

    float acc[4][5][4];
    #pragma unroll
    for (int mu = 0; mu < 4; ++mu)
        #pragma unroll
        for (int nu = 0; nu < 5; ++nu)
            #pragma unroll
            for (int q = 0; q < 4; ++q) acc[mu][nu][q] = 0.f;

    // ---- fills ----
    auto fillA = [&](int s) {
        const uint4* src = srcA + (size_t)s * 2048;
        uint32_t dst = aBufs + (s & 1) * A_STAGE_B;
        #pragma unroll
        for (int i = 0; i < 11; ++i) {
            int idx = tid + i * 192;
            if (idx < 2048) cp16(dst + idx * 16, src + idx);
        }
    };
    auto fillB = [&](int cb) {
        #pragma unroll
        for (int sp = 0; sp < 2; ++sp) {
            const char* src = (const char*)(g_T + sp * T_SPLIT_EL
                              + (((size_t)b * 4 + cb) * T_ROWS + p0) * 64);
            uint32_t dst = bBufs + sp * B_SPLIT_B;
            #pragma unroll
            for (int i = 0; i < 8; ++i) {
                int idx = tid + i * 192;
                if (idx < 1456) cp16(dst + idx * 16, src + (size_t)idx * 16);
            }
        }
    };

    fillA(0); fillB(0); CP_COMMIT();

    int tap = 0, cblk = 0;
    for (int s = 0; s < 36; ++s) {
        __syncthreads();     // all threads done with stage s-1 reads
        if (s > 0 && tap == 0) { fillB(cblk); CP_COMMIT(); }
        if (s + 1 < 36) {
            fillA(s + 1); CP_COMMIT();
            asm volatile("cp.async.wait_group 1;" ::: "memory");
        } else {
            asm volatile("cp.async.wait_group 0;" ::: "memory");
        }
        __syncthreads();     // fills visible to all threads

        const int tapoff = 30 * (tap / 3) + (tap % 3);

        #pragma unroll
        for (int pass = 0; pass < 3; ++pass) {
            const uint32_t aB = aBufs + (s & 1) * A_STAGE_B
                              + ((pass == 2) ? A_SPLIT_B : 0);
            const uint32_t bB = bBufs + ((pass == 1) ? B_SPLIT_B : 0);
            #pragma unroll
            for (int ku = 0; ku < 4; ++ku) {
                uint32_t af[4][4];
                #pragma unroll
                for (int mu = 0; mu < 4; ++mu)
                    lds128(af[mu], aB + (((wm * 4 + mu) * 4 + ku) * 32 + L) * 16);
                uint32_t bfr[5][2];
                #pragma unroll
                for (int nu = 0; nu < 5; ++nu) {
                    int p = tapoff + wn * 40 + nu * 8 + r;
                    uint32_t base = bB + p * 128 + 4 * t;
                    int sw = p & 7;
                    bfr[nu][0] = lds32(base + ((((2 * ku)     ) ^ sw) << 4));
                    bfr[nu][1] = lds32(base + ((((2 * ku) + 1 ) ^ sw) << 4));
                }
                #pragma unroll
                for (int mu = 0; mu < 4; ++mu)
                    #pragma unroll
                    for (int nu = 0; nu < 5; ++nu)
                        mma_bf16(acc[mu][nu], af[mu], bfr[nu]);
            }
        }
        if (++tap == 9) { tap = 0; ++cblk; }
    }

    // ---- epilogue: bias + store (pairs never straddle validity) ----
    #pragma unroll
    for (int mu = 0; mu < 4; ++mu) {
        const int o = mt * 128 + wm * 64 + mu * 16 + r;
        const float bv0 = bias[o], bv1 = bias[o + 8];
        #pragma unroll
        for (int nu = 0; nu < 5; ++nu) {
            int n = ht * 120 + wn * 40 + nu * 8 + 2 * t;
            int oh = n / 30, ow = n % 30;
            if (ow <= 27) {
                float2 v0 = make_float2(acc[mu][nu][0] + bv0,
                                        acc[mu][nu][1] + bv0);
                *(float2*)&out[(((size_t)b * COUT + o) * HH + oh) * WW + ow] = v0;
                float2 v1 = make_float2(acc[mu][nu][2] + bv1,
                                        acc[mu][nu][3] + bv1);
                *(float2*)&out[(((size_t)b * COUT + o + 8) * HH + oh) * WW + ow] = v1;
            }
        }
    }
}

// ---------------------------------------------------------------------------
// Harness entry. Inputs (metadata order): inputs, inputs_se, weight, bias.
// ---------------------------------------------------------------------------
extern "C" void kernel_launch(void* const* d_in, const int* in_sizes, int n_in,
                              void* d_out, int out_size) {
    const float* x    = (const float*)d_in[0];   // [32,256,28,28]
    const float* se   = (const float*)d_in[1];   // [32,8]
    const float* wbk  = (const float*)d_in[2];   // [589824,8]
    const float* bias = (const float*)d_in[3];   // [256]
    float* out = (float*)d_out;                  // [32,256,28,28]

    cudaFuncSetAttribute(conv_mma_kernel,
                         cudaFuncAttributeMaxDynamicSharedMemorySize, DYN_BYTES);

    xprep_kernel<<<dim3(31, 4, BB), 256>>>(x);
    wgen_kernel<<<256, 256>>>(wbk, se);
    pack_kernel<<<9216, 256>>>();
    conv_mma_kernel<<<dim3(7, 2, BB), 192, DYN_BYTES>>>(bias, out);
}

// round 16
// speedup vs baseline: 2.6053x; 1.1133x over previous
#include <cuda_runtime.h>
#include <cuda_bf16.h>
#include <cstdint>

// ---------------------------------------------------------------------------
// DiverseRegDCConv2d via warp-level HMMA (mma.sync m16n8k16 bf16) implicit GEMM.
//   Per sample b:  D[o, n] = sum_{tap,c} W[o,c,tap] * T[n + tapoff(tap), c]
// n indexes the zero-padded 30x30 pixel space (n = oh*30 + ow'), so each tap
// is a row offset (30*kh + kw) into one shared T slab.
// Precision: bf16 hi/lo split, 3 accumulating passes (hh, hl, lh).
// B=32, C=O=256, H=W=28, K=3, NUM=8.
// ---------------------------------------------------------------------------

#define BB   32
#define CIN  256
#define COUT 256
#define HH   28
#define WW   28

typedef unsigned long long ULL;

// intermediate generated weights fp32: [b][o:256][tap:9][c:256]  (75.5 MB)
__device__ float g_wgen[(size_t)BB * 256 * 9 * 256];

// A fragments, mma-ready: [b][mt:2][stage:36][split:2][frag:8][ku:4][lane:32] uint4
__device__ uint4 g_A[(size_t)BB * 2 * 36 * 2 * 1024];          // 75.5 MB

// T slabs: [split:2][b][cblk:4][p:912][c:64] bf16, 128B rows, granule ^ (p&7).
#define T_ROWS 912
#define T_SPLIT_EL ((size_t)BB * 4 * T_ROWS * 64)
__device__ __nv_bfloat16 g_T[2 * T_SPLIT_EL];

// ---------------- helpers ----------------------------------------------------
__device__ __forceinline__ void cp16(uint32_t dst, const void* src) {
    asm volatile("cp.async.ca.shared.global [%0], [%1], 16;\n"
                 :: "r"(dst), "l"(src) : "memory");
}
#define CP_COMMIT() asm volatile("cp.async.commit_group;\n" ::: "memory")
#define CP_WAIT0()  asm volatile("cp.async.wait_group 0;\n" ::: "memory")

__device__ __forceinline__ void lds128(uint32_t* q, uint32_t a) {
    asm volatile("ld.shared.v4.b32 {%0,%1,%2,%3}, [%4];"
                 : "=r"(q[0]), "=r"(q[1]), "=r"(q[2]), "=r"(q[3]) : "r"(a));
}
__device__ __forceinline__ uint32_t lds32(uint32_t a) {
    uint32_t v; asm volatile("ld.shared.b32 %0, [%1];" : "=r"(v) : "r"(a));
    return v;
}
__device__ __forceinline__ void mma_bf16(float* d, const uint32_t* a,
                                         const uint32_t* bfr) {
    asm volatile(
        "mma.sync.aligned.m16n8k16.row.col.f32.bf16.bf16.f32 "
        "{%0,%1,%2,%3}, {%4,%5,%6,%7}, {%8,%9}, {%0,%1,%2,%3};"
        : "+f"(d[0]), "+f"(d[1]), "+f"(d[2]), "+f"(d[3])
        : "r"(a[0]), "r"(a[1]), "r"(a[2]), "r"(a[3]),
          "r"(bfr[0]), "r"(bfr[1]));
}
__device__ __forceinline__ void split2(float x, float y, uint32_t& hi, uint32_t& lo) {
    __nv_bfloat16 h0 = __float2bfloat16(x);
    __nv_bfloat16 h1 = __float2bfloat16(y);
    __nv_bfloat16 l0 = __float2bfloat16(x - __bfloat162float(h0));
    __nv_bfloat16 l1 = __float2bfloat16(y - __bfloat162float(h1));
    hi = ((uint32_t)__bfloat16_as_ushort(h1) << 16) | __bfloat16_as_ushort(h0);
    lo = ((uint32_t)__bfloat16_as_ushort(l1) << 16) | __bfloat16_as_ushort(l0);
}

// ---------------------------------------------------------------------------
// Stage 0: T slabs. Block = (i 0..30, cblk, b); i==30 zeroes guard rows.
// ---------------------------------------------------------------------------
__global__ void xprep_kernel(const float* __restrict__ x) {
    __shared__ float sm[64 * 28];
    const int i = blockIdx.x, cblk = blockIdx.y, b = blockIdx.z;
    const int tid = threadIdx.x;

    if (i == 30) {
        for (int idx = tid; idx < 12 * 64; idx += 256) {
            int rr = idx / 64, slot = idx % 64;
            size_t base = (((size_t)b * 4 + cblk) * T_ROWS + 900 + rr) * 64 + slot;
            g_T[base] = __float2bfloat16(0.f);
            g_T[T_SPLIT_EL + base] = __float2bfloat16(0.f);
        }
        return;
    }
    const bool iv = (i >= 1 && i <= 28);
    if (iv) {
        for (int idx = tid; idx < 64 * 28; idx += 256) {
            int c_l = idx / 28, j1 = idx % 28;
            sm[idx] = x[(((size_t)b * 256 + cblk * 64 + c_l) * HH + (i - 1)) * WW + j1];
        }
    }
    __syncthreads();
    for (int idx = tid; idx < 30 * 64; idx += 256) {
        int j = idx / 64, c_l = idx % 64;
        float v = 0.f;
        if (iv && j >= 1 && j <= 28) v = sm[c_l * 28 + (j - 1)];
        int p = i * 30 + j;
        int slot = (((c_l >> 3) ^ (p & 7)) << 3) | (c_l & 7);
        __nv_bfloat16 hi = __float2bfloat16(v);
        __nv_bfloat16 lo = __float2bfloat16(v - __bfloat162float(hi));
        size_t base = (((size_t)b * 4 + cblk) * T_ROWS + p) * 64 + slot;
        g_T[base] = hi;
        g_T[T_SPLIT_EL + base] = lo;
    }
}

// ---------------------------------------------------------------------------
// Stage 1: weight generation. Thread = (o, c), bank row in regs, loops b.
// ---------------------------------------------------------------------------
__global__ void wgen_kernel(const float* __restrict__ wbank,
                            const float* __restrict__ se) {
    __shared__ float s_se[256];
    const int tid = threadIdx.x;
    s_se[tid] = se[tid];
    __syncthreads();

    const int o = (blockIdx.x >> 3) * 8 + (tid >> 5);
    const int c = (blockIdx.x & 7) * 32 + (tid & 31);

    const float4* src = (const float4*)wbank + (size_t)(o * 256 + c) * 18;
    float4 w4[18];
    #pragma unroll
    for (int i = 0; i < 18; ++i) w4[i] = src[i];
    const float* w = (const float*)w4;

    for (int b = 0; b < BB; ++b) {
        const float* s = &s_se[b * 8];
        #pragma unroll
        for (int t = 0; t < 9; ++t) {
            float v = w[t * 8 + 0] * s[0];
            v = fmaf(w[t * 8 + 1], s[1], v);
            v = fmaf(w[t * 8 + 2], s[2], v);
            v = fmaf(w[t * 8 + 3], s[3], v);
            v = fmaf(w[t * 8 + 4], s[4], v);
            v = fmaf(w[t * 8 + 5], s[5], v);
            v = fmaf(w[t * 8 + 6], s[6], v);
            v = fmaf(w[t * 8 + 7], s[7], v);
            g_wgen[(((size_t)b * 256 + o) * 9 + t) * 256 + c] = v;
        }
    }
}

// ---------------------------------------------------------------------------
// Stage 2: pack wgen into mma A-fragment order (hi & lo splits).
// ---------------------------------------------------------------------------
__global__ void pack_kernel() {
    int idx = blockIdx.x * 256 + threadIdx.x;     // < 2,359,296
    int lane = idx & 31;  int x1 = idx >> 5;
    int ku   = x1 & 3;    int x2 = x1 >> 2;
    int frag = x2 & 7;    int x3 = x2 >> 3;
    int tap  = x3 % 9;    int x4 = x3 / 9;
    int cblk = x4 & 3;    int x5 = x4 >> 2;
    int mt   = x5 & 1;    int b  = x5 >> 1;

    int r = lane >> 2, t = lane & 3;
    int o0 = mt * 128 + frag * 16 + r;
    int c0 = cblk * 64 + ku * 16 + 2 * t;
    size_t row0 = (((size_t)b * 256 + o0) * 9 + tap) * 256;
    size_t row8 = row0 + (size_t)8 * 9 * 256;
    float2 v0 = *(const float2*)&g_wgen[row0 + c0];
    float2 v1 = *(const float2*)&g_wgen[row8 + c0];
    float2 v2 = *(const float2*)&g_wgen[row0 + c0 + 8];
    float2 v3 = *(const float2*)&g_wgen[row8 + c0 + 8];

    uint4 hi, lo;
    split2(v0.x, v0.y, hi.x, lo.x);
    split2(v1.x, v1.y, hi.y, lo.y);
    split2(v2.x, v2.y, hi.z, lo.z);
    split2(v3.x, v3.y, hi.w, lo.w);

    size_t sb = (((size_t)(b * 2 + mt) * 36 + (cblk * 9 + tap)) * 2) * 1024
                + (frag * 4 + ku) * 32 + lane;
    g_A[sb] = hi;
    g_A[sb + 1024] = lo;
}

// ---------------------------------------------------------------------------
// Stage 3: HMMA GEMM. Grid (ht:7, mt:2, b:32), 192 thr = 6 warps (2M x 3N).
// Warp tile m64 x n40. 36 k-stages, one __syncthreads per stage; fragment
// reuse: per ku load Ah once (hh+hl passes), Bh/Bl once, then Al (lh pass).
// ---------------------------------------------------------------------------
#define A_SPLIT_B 16384
#define A_STAGE_B 32768
#define B_SPLIT_B 23296                    // 182 * 128
#define DYN_BYTES (1024 + 2 * A_STAGE_B + 2 * B_SPLIT_B)   // 113152

__global__ __launch_bounds__(192, 2)
void conv_mma_kernel(const float* __restrict__ bias,
                     float* __restrict__ out) {
    extern __shared__ char dyn[];
    const int tid = threadIdx.x;
    const int L = tid & 31, wid = tid >> 5;
    const int wm = wid & 1, wn = wid >> 1;    // wn 0..2
    const int r = L >> 2, t = L & 3;
    const int ht = blockIdx.x, mt = blockIdx.y, b = blockIdx.z;

    const uint32_t dynu = (uint32_t)__cvta_generic_to_shared(dyn);
    const uint32_t al = (dynu + 1023) & ~1023u;
    const uint32_t aBufs = al;
    const uint32_t bBufs = al + 2 * A_STAGE_B;

    const uint4* srcA = g_A + ((size_t)(b * 2 + mt) * 36) * 2048;
    const int p0 = ht * 120;

    float acc[4][5][4];
    #pragma unroll
    for (int mu = 0; mu < 4; ++mu)
        #pragma unroll
        for (int nu = 0; nu < 5; ++nu)
            #pragma unroll
            for (int q = 0; q < 4; ++q) acc[mu][nu][q] = 0.f;

    auto fillA = [&](int s) {
        const uint4* src = srcA + (size_t)s * 2048;
        uint32_t dst = aBufs + (s & 1) * A_STAGE_B;
        #pragma unroll
        for (int i = 0; i < 11; ++i) {
            int idx = tid + i * 192;
            if (idx < 2048) cp16(dst + idx * 16, src + idx);
        }
    };
    auto fillB = [&](int cb) {
        #pragma unroll
        for (int sp = 0; sp < 2; ++sp) {
            const char* src = (const char*)(g_T + sp * T_SPLIT_EL
                              + (((size_t)b * 4 + cb) * T_ROWS + p0) * 64);
            uint32_t dst = bBufs + sp * B_SPLIT_B;
            #pragma unroll
            for (int i = 0; i < 8; ++i) {
                int idx = tid + i * 192;
                if (idx < 1456) cp16(dst + idx * 16, src + (size_t)idx * 16);
            }
        }
    };

    // prologue: A(0) + B(0) as one group
    fillA(0); fillB(0); CP_COMMIT();

    int tap = 0, cblk = 0;
    for (int s = 0; s < 36; ++s) {
        CP_WAIT0();          // group(s-1): A(s) landed (prologue: A0+B0)
        __syncthreads();     // visible to all; all done with compute(s-1)

        if (s > 0 && tap == 0) {       // B slab turnover (s = 9, 18, 27)
            fillB(cblk); CP_COMMIT();
            CP_WAIT0();
            __syncthreads();
        }
        if (s + 1 < 36) { fillA(s + 1); CP_COMMIT(); }   // overlaps compute(s)

        const uint32_t aB = aBufs + (s & 1) * A_STAGE_B;
        const int tapoff = 30 * (tap / 3) + (tap % 3);

        #pragma unroll
        for (int ku = 0; ku < 4; ++ku) {
            // A-hi fragments (reused by hh and hl passes)
            uint32_t af[4][4];
            #pragma unroll
            for (int mu = 0; mu < 4; ++mu)
                lds128(af[mu], aB + (((wm * 4 + mu) * 4 + ku) * 32 + L) * 16);
            // B hi + lo fragments (hi reused by hh and lh passes)
            uint32_t bh[5][2], bl[5][2];
            #pragma unroll
            for (int nu = 0; nu < 5; ++nu) {
                int p = tapoff + wn * 40 + nu * 8 + r;
                int sw = p & 7;
                uint32_t o0 = (uint32_t)((((2 * ku)    ) ^ sw) << 4);
                uint32_t o1 = (uint32_t)((((2 * ku) + 1) ^ sw) << 4);
                uint32_t baseH = bBufs + p * 128 + 4 * t;
                uint32_t baseL = baseH + B_SPLIT_B;
                bh[nu][0] = lds32(baseH + o0);
                bh[nu][1] = lds32(baseH + o1);
                bl[nu][0] = lds32(baseL + o0);
                bl[nu][1] = lds32(baseL + o1);
            }
            // pass hh
            #pragma unroll
            for (int mu = 0; mu < 4; ++mu)
                #pragma unroll
                for (int nu = 0; nu < 5; ++nu)
                    mma_bf16(acc[mu][nu], af[mu], bh[nu]);
            // pass hl (same A-hi)
            #pragma unroll
            for (int mu = 0; mu < 4; ++mu)
                #pragma unroll
                for (int nu = 0; nu < 5; ++nu)
                    mma_bf16(acc[mu][nu], af[mu], bl[nu]);
            // A-lo fragments, pass lh (same B-hi)
            #pragma unroll
            for (int mu = 0; mu < 4; ++mu)
                lds128(af[mu], aB + A_SPLIT_B
                               + (((wm * 4 + mu) * 4 + ku) * 32 + L) * 16);
            #pragma unroll
            for (int mu = 0; mu < 4; ++mu)
                #pragma unroll
                for (int nu = 0; nu < 5; ++nu)
                    mma_bf16(acc[mu][nu], af[mu], bh[nu]);
        }

        if (++tap == 9) { tap = 0; ++cblk; }
    }

    // ---- epilogue: bias + store (pairs never straddle validity) ----
    #pragma unroll
    for (int mu = 0; mu < 4; ++mu) {
        const int o = mt * 128 + wm * 64 + mu * 16 + r;
        const float bv0 = bias[o], bv1 = bias[o + 8];
        #pragma unroll
        for (int nu = 0; nu < 5; ++nu) {
            int n = ht * 120 + wn * 40 + nu * 8 + 2 * t;
            int oh = n / 30, ow = n % 30;
            if (ow <= 27) {
                float2 v0 = make_float2(acc[mu][nu][0] + bv0,
                                        acc[mu][nu][1] + bv0);
                *(float2*)&out[(((size_t)b * COUT + o) * HH + oh) * WW + ow] = v0;
                float2 v1 = make_float2(acc[mu][nu][2] + bv1,
                                        acc[mu][nu][3] + bv1);
                *(float2*)&out[(((size_t)b * COUT + o + 8) * HH + oh) * WW + ow] = v1;
            }
        }
    }
}

// ---------------------------------------------------------------------------
// Harness entry. Inputs (metadata order): inputs, inputs_se, weight, bias.
// ---------------------------------------------------------------------------
extern "C" void kernel_launch(void* const* d_in, const int* in_sizes, int n_in,
                              void* d_out, int out_size) {
    const float* x    = (const float*)d_in[0];   // [32,256,28,28]
    const float* se   = (const float*)d_in[1];   // [32,8]
    const float* wbk  = (const float*)d_in[2];   // [589824,8]
    const float* bias = (const float*)d_in[3];   // [256]
    float* out = (float*)d_out;                  // [32,256,28,28]

    cudaFuncSetAttribute(conv_mma_kernel,
                         cudaFuncAttributeMaxDynamicSharedMemorySize, DYN_BYTES);

    xprep_kernel<<<dim3(31, 4, BB), 256>>>(x);
    wgen_kernel<<<256, 256>>>(wbk, se);
    pack_kernel<<<9216, 256>>>();
    conv_mma_kernel<<<dim3(7, 2, BB), 192, DYN_BYTES>>>(bias, out);
}

// round 17
// speedup vs baseline: 2.9549x; 1.1342x over previous
#include <cuda_runtime.h>
#include <cuda_bf16.h>
#include <cstdint>

// ---------------------------------------------------------------------------
// DiverseRegDCConv2d via warp-level HMMA (mma.sync m16n8k16 bf16) implicit GEMM.
//   Per sample b:  D[o, n] = sum_{tap,c} W[o,c,tap] * T[n + tapoff(tap), c]
// n indexes the zero-padded 30x30 pixel space; each tap is a row offset
// (30*kh + kw) into one shared T slab.  bf16 hi/lo split, 3 passes.
// A fragments stream straight from gmem (fragment-ordered, coalesced LDG.128);
// B slabs double-buffered in smem; one __syncthreads per 9 stages.
// ---------------------------------------------------------------------------

#define BB   32
#define CIN  256
#define COUT 256
#define HH   28
#define WW   28

typedef unsigned long long ULL;

// A fragments, mma-ready: [b][mt:2][stage:36][split:2][frag:8][ku:4][lane:32] uint4
__device__ uint4 g_A[(size_t)BB * 2 * 36 * 2 * 1024];          // 75.5 MB

// T slabs: [split:2][b][cblk:4][p:912][c:64] bf16, 128B rows, granule ^ (p&7).
#define T_ROWS 912
#define T_SPLIT_EL ((size_t)BB * 4 * T_ROWS * 64)
__device__ __nv_bfloat16 g_T[2 * T_SPLIT_EL];

// ---------------- helpers ----------------------------------------------------
__device__ __forceinline__ void cp16(uint32_t dst, const void* src) {
    asm volatile("cp.async.ca.shared.global [%0], [%1], 16;\n"
                 :: "r"(dst), "l"(src) : "memory");
}
#define CP_COMMIT() asm volatile("cp.async.commit_group;\n" ::: "memory")
#define CP_WAIT0()  asm volatile("cp.async.wait_group 0;\n" ::: "memory")

__device__ __forceinline__ uint32_t lds32(uint32_t a) {
    uint32_t v; asm volatile("ld.shared.b32 %0, [%1];" : "=r"(v) : "r"(a));
    return v;
}
__device__ __forceinline__ void mma_bf16(float* d, const uint4& a,
                                         const uint32_t* bfr) {
    asm volatile(
        "mma.sync.aligned.m16n8k16.row.col.f32.bf16.bf16.f32 "
        "{%0,%1,%2,%3}, {%4,%5,%6,%7}, {%8,%9}, {%0,%1,%2,%3};"
        : "+f"(d[0]), "+f"(d[1]), "+f"(d[2]), "+f"(d[3])
        : "r"(a.x), "r"(a.y), "r"(a.z), "r"(a.w),
          "r"(bfr[0]), "r"(bfr[1]));
}
__device__ __forceinline__ void split2(float x, float y, uint32_t& hi, uint32_t& lo) {
    __nv_bfloat16 h0 = __float2bfloat16(x);
    __nv_bfloat16 h1 = __float2bfloat16(y);
    __nv_bfloat16 l0 = __float2bfloat16(x - __bfloat162float(h0));
    __nv_bfloat16 l1 = __float2bfloat16(y - __bfloat162float(h1));
    hi = ((uint32_t)__bfloat16_as_ushort(h1) << 16) | __bfloat16_as_ushort(h0);
    lo = ((uint32_t)__bfloat16_as_ushort(l1) << 16) | __bfloat16_as_ushort(l0);
}

// ---------------------------------------------------------------------------
// Stage 0: T slabs. Block = (i 0..30, cblk, b); i==30 zeroes guard rows.
// ---------------------------------------------------------------------------
__global__ void xprep_kernel(const float* __restrict__ x) {
    __shared__ float sm[64 * 28];
    const int i = blockIdx.x, cblk = blockIdx.y, b = blockIdx.z;
    const int tid = threadIdx.x;

    if (i == 30) {
        for (int idx = tid; idx < 12 * 64; idx += 256) {
            int rr = idx / 64, slot = idx % 64;
            size_t base = (((size_t)b * 4 + cblk) * T_ROWS + 900 + rr) * 64 + slot;
            g_T[base] = __float2bfloat16(0.f);
            g_T[T_SPLIT_EL + base] = __float2bfloat16(0.f);
        }
        return;
    }
    const bool iv = (i >= 1 && i <= 28);
    if (iv) {
        for (int idx = tid; idx < 64 * 28; idx += 256) {
            int c_l = idx / 28, j1 = idx % 28;
            sm[idx] = x[(((size_t)b * 256 + cblk * 64 + c_l) * HH + (i - 1)) * WW + j1];
        }
    }
    __syncthreads();
    for (int idx = tid; idx < 30 * 64; idx += 256) {
        int j = idx / 64, c_l = idx % 64;
        float v = 0.f;
        if (iv && j >= 1 && j <= 28) v = sm[c_l * 28 + (j - 1)];
        int p = i * 30 + j;
        int slot = (((c_l >> 3) ^ (p & 7)) << 3) | (c_l & 7);
        __nv_bfloat16 hi = __float2bfloat16(v);
        __nv_bfloat16 lo = __float2bfloat16(v - __bfloat162float(hi));
        size_t base = (((size_t)b * 4 + cblk) * T_ROWS + p) * 64 + slot;
        g_T[base] = hi;
        g_T[T_SPLIT_EL + base] = lo;
    }
}

// ---------------------------------------------------------------------------
// Stage 1 (fused wgen+pack): generate weights AND write mma-ready fragments.
// Grid 288 x 256: block -> (chunk:4, mt:2, stage:36); thread -> (frag,ku,lane)
// within chunk. Thread holds its 8 bank rows (64 floats), loops 32 samples.
// ---------------------------------------------------------------------------
__global__ void wpack_kernel(const float* __restrict__ wbank,
                             const float* __restrict__ se) {
    __shared__ float s_se[256];
    const int tid = threadIdx.x;
    s_se[tid] = se[tid];
    __syncthreads();

    const int stage = blockIdx.x % 36;
    const int mt    = (blockIdx.x / 36) & 1;
    const int chunk = blockIdx.x / 72;           // 0..3
    const int fkl   = chunk * 256 + tid;         // 0..1023
    const int frag  = fkl >> 7;
    const int ku    = (fkl >> 5) & 3;
    const int lane  = fkl & 31;
    const int cblk  = stage / 9, tap = stage % 9;
    const int r = lane >> 2, t = lane & 3;
    const int o0 = mt * 128 + frag * 16 + r;
    const int c0 = cblk * 64 + ku * 16 + 2 * t;

    // 8 bank rows: (o0/o0+8) x (c0, c0+1, c0+8, c0+9), 8 floats each
    float w[8][8];
    #pragma unroll
    for (int oo = 0; oo < 2; ++oo) {
        #pragma unroll
        for (int cc = 0; cc < 4; ++cc) {
            int c = c0 + ((cc & 1) ? 1 : 0) + ((cc & 2) ? 8 : 0);
            const float4* src = (const float4*)wbank
                + ((size_t)((o0 + 8 * oo) * 256 + c) * 9 + tap) * 2;
            float4 a0 = src[0], a1 = src[1];
            float* d = w[oo * 4 + cc];
            d[0] = a0.x; d[1] = a0.y; d[2] = a0.z; d[3] = a0.w;
            d[4] = a1.x; d[5] = a1.y; d[6] = a1.z; d[7] = a1.w;
        }
    }

    uint4* dst = g_A + ((size_t)mt * 36 + stage) * 2048 + fkl;
    for (int b = 0; b < BB; ++b) {
        const float* s = &s_se[b * 8];
        float v[8];
        #pragma unroll
        for (int k = 0; k < 8; ++k) {
            float a = w[k][0] * s[0];
            a = fmaf(w[k][1], s[1], a);
            a = fmaf(w[k][2], s[2], a);
            a = fmaf(w[k][3], s[3], a);
            a = fmaf(w[k][4], s[4], a);
            a = fmaf(w[k][5], s[5], a);
            a = fmaf(w[k][6], s[6], a);
            a = fmaf(w[k][7], s[7], a);
            v[k] = a;
        }
        uint4 hi, lo;
        split2(v[0], v[1], hi.x, lo.x);   // reg0: A[r][2t,2t+1]
        split2(v[4], v[5], hi.y, lo.y);   // reg1: A[r+8][2t,2t+1]
        split2(v[2], v[3], hi.z, lo.z);   // reg2: A[r][2t+8,2t+9]
        split2(v[6], v[7], hi.w, lo.w);   // reg3: A[r+8][2t+8,2t+9]
        dst[(size_t)b * (2 * 36 * 2048)] = hi;
        dst[(size_t)b * (2 * 36 * 2048) + 1024] = lo;
    }
}

// ---------------------------------------------------------------------------
// Stage 2: HMMA GEMM. Grid (ht:7, mt:2, b:32), 192 thr = 6 warps (2M x 3N).
// Warp tile m64 x n40. A fragments via direct coalesced LDG.128 (no smem);
// B slabs double-buffered; ONE __syncthreads per cblk (9 stages).
// ---------------------------------------------------------------------------
#define B_SPLIT_B 23296                    // 182 rows * 128 B
#define B_BUF_B   (2 * B_SPLIT_B)
#define DYN_BYTES (1024 + 2 * B_BUF_B)     // 94208

__global__ __launch_bounds__(192, 2)
void conv_mma_kernel(const float* __restrict__ bias,
                     float* __restrict__ out) {
    extern __shared__ char dyn[];
    const int tid = threadIdx.x;
    const int L = tid & 31, wid = tid >> 5;
    const int wm = wid & 1, wn = wid >> 1;    // wn 0..2
    const int r = L >> 2, t = L & 3;
    const int ht = blockIdx.x, mt = blockIdx.y, b = blockIdx.z;

    const uint32_t dynu = (uint32_t)__cvta_generic_to_shared(dyn);
    const uint32_t bBufs = (dynu + 1023) & ~1023u;

    // A fragment base for this warp: lane-resolved, advances by 2048/stage.
    const uint4* aBase = g_A + ((size_t)(b * 2 + mt) * 36) * 2048
                         + (wm * 4) * 128 + L;
    const int p0 = ht * 120;

    float acc[4][5][4];
    #pragma unroll
    for (int mu = 0; mu < 4; ++mu)
        #pragma unroll
        for (int nu = 0; nu < 5; ++nu)
            #pragma unroll
            for (int q = 0; q < 4; ++q) acc[mu][nu][q] = 0.f;

    auto fillB = [&](int cb) {
        const uint32_t dst0 = bBufs + (cb & 1) * B_BUF_B;
        #pragma unroll
        for (int sp = 0; sp < 2; ++sp) {
            const char* src = (const char*)(g_T + sp * T_SPLIT_EL
                              + (((size_t)b * 4 + cb) * T_ROWS + p0) * 64);
            uint32_t dst = dst0 + sp * B_SPLIT_B;
            #pragma unroll
            for (int i = 0; i < 8; ++i) {
                int idx = tid + i * 192;
                if (idx < 1456) cp16(dst + idx * 16, src + (size_t)idx * 16);
            }
        }
    };

    fillB(0); CP_COMMIT();

    for (int cb = 0; cb < 4; ++cb) {
        CP_WAIT0();          // B(cb) landed (and any older group)
        __syncthreads();     // visible to all; all warps done with buf (cb&1)

        if (cb < 3) { fillB(cb + 1); CP_COMMIT(); }   // opposite parity buffer

        const uint32_t bH = bBufs + (cb & 1) * B_BUF_B;
        const uint32_t bL = bH + B_SPLIT_B;

        for (int tap = 0; tap < 9; ++tap) {
            const uint4* aS = aBase + (size_t)(cb * 9 + tap) * 2048;
            const int tapoff = 30 * (tap / 3) + (tap % 3);

            #pragma unroll
            for (int ku = 0; ku < 4; ++ku) {
                uint4 ah[4], al[4];
                #pragma unroll
                for (int mu = 0; mu < 4; ++mu) {
                    ah[mu] = __ldg(aS + (mu * 4 + ku) * 32);
                    al[mu] = __ldg(aS + 1024 + (mu * 4 + ku) * 32);
                }
                uint32_t bh[5][2], bl[5][2];
                #pragma unroll
                for (int nu = 0; nu < 5; ++nu) {
                    int p = tapoff + wn * 40 + nu * 8 + r;
                    int sw = p & 7;
                    uint32_t o0 = (uint32_t)((((2 * ku)    ) ^ sw) << 4);
                    uint32_t o1 = (uint32_t)((((2 * ku) + 1) ^ sw) << 4);
                    uint32_t baseH = bH + p * 128 + 4 * t;
                    uint32_t baseL = bL + p * 128 + 4 * t;
                    bh[nu][0] = lds32(baseH + o0);
                    bh[nu][1] = lds32(baseH + o1);
                    bl[nu][0] = lds32(baseL + o0);
                    bl[nu][1] = lds32(baseL + o1);
                }
                #pragma unroll
                for (int mu = 0; mu < 4; ++mu)
                    #pragma unroll
                    for (int nu = 0; nu < 5; ++nu)
                        mma_bf16(acc[mu][nu], ah[mu], bh[nu]);   // hh
                #pragma unroll
                for (int mu = 0; mu < 4; ++mu)
                    #pragma unroll
                    for (int nu = 0; nu < 5; ++nu)
                        mma_bf16(acc[mu][nu], ah[mu], bl[nu]);   // hl
                #pragma unroll
                for (int mu = 0; mu < 4; ++mu)
                    #pragma unroll
                    for (int nu = 0; nu < 5; ++nu)
                        mma_bf16(acc[mu][nu], al[mu], bh[nu]);   // lh
            }
        }
    }

    // ---- epilogue: bias + store (pairs never straddle validity) ----
    #pragma unroll
    for (int mu = 0; mu < 4; ++mu) {
        const int o = mt * 128 + wm * 64 + mu * 16 + r;
        const float bv0 = bias[o], bv1 = bias[o + 8];
        #pragma unroll
        for (int nu = 0; nu < 5; ++nu) {
            int n = ht * 120 + wn * 40 + nu * 8 + 2 * t;
            int oh = n / 30, ow = n % 30;
            if (ow <= 27) {
                float2 v0 = make_float2(acc[mu][nu][0] + bv0,
                                        acc[mu][nu][1] + bv0);
                *(float2*)&out[(((size_t)b * COUT + o) * HH + oh) * WW + ow] = v0;
                float2 v1 = make_float2(acc[mu][nu][2] + bv1,
                                        acc[mu][nu][3] + bv1);
                *(float2*)&out[(((size_t)b * COUT + o + 8) * HH + oh) * WW + ow] = v1;
            }
        }
    }
}

// ---------------------------------------------------------------------------
// Harness entry. Inputs (metadata order): inputs, inputs_se, weight, bias.
// ---------------------------------------------------------------------------
extern "C" void kernel_launch(void* const* d_in, const int* in_sizes, int n_in,
                              void* d_out, int out_size) {
    const float* x    = (const float*)d_in[0];   // [32,256,28,28]
    const float* se   = (const float*)d_in[1];   // [32,8]
    const float* wbk  = (const float*)d_in[2];   // [589824,8]
    const float* bias = (const float*)d_in[3];   // [256]
    float* out = (float*)d_out;                  // [32,256,28,28]

    cudaFuncSetAttribute(conv_mma_kernel,
                         cudaFuncAttributeMaxDynamicSharedMemorySize, DYN_BYTES);

    xprep_kernel<<<dim3(31, 4, BB), 256>>>(x);
    wpack_kernel<<<288, 256>>>(wbk, se);
    conv_mma_kernel<<<dim3(7, 2, BB), 192, DYN_BYTES>>>(bias, out);
}